// round 2
// baseline (speedup 1.0000x reference)
#include <cuda_runtime.h>
#include <math.h>
#include <stdint.h>

// ---------------- problem constants ----------------
#define H_IN 2048
#define W_IN 2048
#define P1   1023            // after conv1(2046) + maxpool2
#define C2   1021            // after conv2
#define C3   1019            // after conv3
#define NPIX (C3*C3)         // 1038361
#define NBINS 8192
#define CANDMAX 4096
#define KTOP 512

// ---------------- scratch (device globals) ----------
__device__ float g_pool1[10 * P1 * P1];
__device__ float g_h2[16 * C2 * C2];
__device__ float g_prob[NPIX];
__device__ float4 g_reg[NPIX];
__device__ int   g_hist[NBINS];
__device__ int   g_cut;
__device__ int   g_cnt;
__device__ unsigned long long g_cand[CANDMAX];
__device__ float g_box5[KTOP * 5];
__device__ unsigned g_mask0[KTOP * 16];
__device__ unsigned g_mask1[KTOP * 16];
__device__ float g_stage[6632];

// ---------------- packed constant weights ----------------
#define OW1 0
#define OB1 270
#define OP1 280
#define OW2 290
#define OB2 1730
#define OP2 1746
#define OW3 1762
#define OB3 6370
#define OP3 6402
#define OWA 6434
#define OBA 6498
#define OWB 6500
#define OBB 6628
#define NCONST 6632
__constant__ float cAll[NCONST];

#define CW1(i) cAll[OW1 + (i)]
#define CB1(i) cAll[OB1 + (i)]
#define CP1(i) cAll[OP1 + (i)]
#define CW2(i) cAll[OW2 + (i)]
#define CB2(i) cAll[OB2 + (i)]
#define CP2(i) cAll[OP2 + (i)]
#define CW3(i) cAll[OW3 + (i)]
#define CB3(i) cAll[OB3 + (i)]
#define CP3(i) cAll[OP3 + (i)]
#define CWA(i) cAll[OWA + (i)]
#define CBA(i) cAll[OBA + (i)]
#define CWB(i) cAll[OWB + (i)]
#define CBB(i) cAll[OBB + (i)]

// ============ KP: pack all weights into one staging buffer ============
__global__ void kpack(const float* w1, const float* b1, const float* p1,
                      const float* w2, const float* b2, const float* p2,
                      const float* w3, const float* b3, const float* p3,
                      const float* wa, const float* ba,
                      const float* wb, const float* bb) {
    int t = threadIdx.x;
    for (int i = t; i < 270; i += 256) g_stage[OW1 + i] = w1[i];
    if (t < 10) g_stage[OB1 + t] = b1[t];
    if (t < 10) g_stage[OP1 + t] = p1[t];
    for (int i = t; i < 1440; i += 256) g_stage[OW2 + i] = w2[i];
    if (t < 16) g_stage[OB2 + t] = b2[t];
    if (t < 16) g_stage[OP2 + t] = p2[t];
    for (int i = t; i < 4608; i += 256) g_stage[OW3 + i] = w3[i];
    if (t < 32) g_stage[OB3 + t] = b3[t];
    if (t < 32) g_stage[OP3 + t] = p3[t];
    if (t < 64) g_stage[OWA + t] = wa[t];
    if (t < 2)  g_stage[OBA + t] = ba[t];
    for (int i = t; i < 128; i += 256) g_stage[OWB + i] = wb[i];
    if (t < 4)  g_stage[OBB + t] = bb[t];
}

// ============ K1: conv1(3->10,3x3) + PReLU + maxpool2 fused ============
__global__ __launch_bounds__(256) void k1(const float* __restrict__ x) {
    int j = blockIdx.x * 16 + threadIdx.x;
    int i = blockIdx.y * 16 + threadIdx.y;
    if (i >= P1 || j >= P1) return;

    float p[3][4][4];
#pragma unroll
    for (int c = 0; c < 3; c++) {
        const float* xp = x + c * H_IN * W_IN + (2 * i) * W_IN + 2 * j;
#pragma unroll
        for (int a = 0; a < 4; a++) {
            const float2* rp = reinterpret_cast<const float2*>(xp + a * W_IN);
            float2 u = rp[0], v = rp[1];
            p[c][a][0] = u.x; p[c][a][1] = u.y; p[c][a][2] = v.x; p[c][a][3] = v.y;
        }
    }

#pragma unroll
    for (int co = 0; co < 10; co++) {
        float bb = CB1(co);
        float a00 = bb, a01 = bb, a10 = bb, a11 = bb;
#pragma unroll
        for (int c = 0; c < 3; c++)
#pragma unroll
            for (int dy = 0; dy < 3; dy++)
#pragma unroll
                for (int dx = 0; dx < 3; dx++) {
                    float w = CW1(((co * 3 + c) * 3 + dy) * 3 + dx);
                    a00 += p[c][dy][dx] * w;
                    a01 += p[c][dy][dx + 1] * w;
                    a10 += p[c][dy + 1][dx] * w;
                    a11 += p[c][dy + 1][dx + 1] * w;
                }
        float al = CP1(co);
        a00 = (a00 >= 0.f) ? a00 : al * a00;
        a01 = (a01 >= 0.f) ? a01 : al * a01;
        a10 = (a10 >= 0.f) ? a10 : al * a10;
        a11 = (a11 >= 0.f) ? a11 : al * a11;
        g_pool1[co * P1 * P1 + i * P1 + j] = fmaxf(fmaxf(a00, a01), fmaxf(a10, a11));
    }
}

// ============ K2: conv2(10->16,3x3) + PReLU, 2 px/thread ============
__global__ __launch_bounds__(256, 3) void k2() {
    __shared__ float s[10][18][36];
    int tx = threadIdx.x, ty = threadIdx.y;
    int tid = ty * 16 + tx;
    int ox0 = blockIdx.x * 32, oy0 = blockIdx.y * 16;

    for (int idx = tid; idx < 10 * 18 * 34; idx += 256) {
        int c = idx / 612;
        int rem = idx - c * 612;
        int r = rem / 34;
        int cc = rem - r * 34;
        int gy = oy0 + r, gx = ox0 + cc;
        s[c][r][cc] = (gy < P1 && gx < P1) ? g_pool1[c * P1 * P1 + gy * P1 + gx] : 0.f;
    }
    __syncthreads();

    int ox = ox0 + tx * 2, oy = oy0 + ty;

    float acc0[16], acc1[16];
#pragma unroll
    for (int o = 0; o < 16; o++) { acc0[o] = CB2(o); acc1[o] = CB2(o); }

    for (int c = 0; c < 10; c++) {
        float r[3][4];
#pragma unroll
        for (int dy = 0; dy < 3; dy++) {
            const float2* rp = reinterpret_cast<const float2*>(&s[c][ty + dy][tx * 2]);
            float2 A = rp[0], B = rp[1];
            r[dy][0] = A.x; r[dy][1] = A.y; r[dy][2] = B.x; r[dy][3] = B.y;
        }
        int wb = c * 9;
#pragma unroll
        for (int o = 0; o < 16; o++)
#pragma unroll
            for (int dy = 0; dy < 3; dy++)
#pragma unroll
                for (int dx = 0; dx < 3; dx++) {
                    float w = CW2(o * 90 + wb + dy * 3 + dx);
                    acc0[o] += r[dy][dx] * w;
                    acc1[o] += r[dy][dx + 1] * w;
                }
    }

    if (oy < C2) {
        int base = oy * C2 + ox;
#pragma unroll
        for (int o = 0; o < 16; o++) {
            float v0 = acc0[o], v1 = acc1[o];
            float al = CP2(o);
            v0 = (v0 >= 0.f) ? v0 : al * v0;
            v1 = (v1 >= 0.f) ? v1 : al * v1;
            if (ox < C2)     g_h2[o * C2 * C2 + base] = v0;
            if (ox + 1 < C2) g_h2[o * C2 * C2 + base + 1] = v1;
        }
    }
}

// ============ K3: conv3(16->32) + PReLU + heads + softmax + hist, 2 px/thread ============
__global__ __launch_bounds__(256, 2) void k3() {
    __shared__ float s[16][18][36];
    int tx = threadIdx.x, ty = threadIdx.y;
    int tid = ty * 16 + tx;
    int ox0 = blockIdx.x * 32, oy0 = blockIdx.y * 16;

    for (int idx = tid; idx < 16 * 18 * 34; idx += 256) {
        int c = idx / 612;
        int rem = idx - c * 612;
        int r = rem / 34;
        int cc = rem - r * 34;
        int gy = oy0 + r, gx = ox0 + cc;
        s[c][r][cc] = (gy < C2 && gx < C2) ? g_h2[c * C2 * C2 + gy * C2 + gx] : 0.f;
    }
    __syncthreads();

    int ox = ox0 + tx * 2, oy = oy0 + ty;

    float acc0[32], acc1[32];
#pragma unroll
    for (int o = 0; o < 32; o++) { acc0[o] = CB3(o); acc1[o] = CB3(o); }

    for (int c = 0; c < 16; c++) {
        float r[3][4];
#pragma unroll
        for (int dy = 0; dy < 3; dy++) {
            const float2* rp = reinterpret_cast<const float2*>(&s[c][ty + dy][tx * 2]);
            float2 A = rp[0], B = rp[1];
            r[dy][0] = A.x; r[dy][1] = A.y; r[dy][2] = B.x; r[dy][3] = B.y;
        }
        int wb = c * 9;
#pragma unroll
        for (int o = 0; o < 32; o++)
#pragma unroll
            for (int dy = 0; dy < 3; dy++)
#pragma unroll
                for (int dx = 0; dx < 3; dx++) {
                    float w = CW3(o * 144 + wb + dy * 3 + dx);
                    acc0[o] += r[dy][dx] * w;
                    acc1[o] += r[dy][dx + 1] * w;
                }
    }

#pragma unroll
    for (int o = 0; o < 32; o++) {
        float al = CP3(o);
        float v0 = acc0[o], v1 = acc1[o];
        acc0[o] = (v0 >= 0.f) ? v0 : al * v0;
        acc1[o] = (v1 >= 0.f) ? v1 : al * v1;
    }

    if (oy >= C3) return;

#pragma unroll
    for (int px = 0; px < 2; px++) {
        int oxx = ox + px;
        if (oxx >= C3) break;
        float c0 = CBA(0), c1 = CBA(1);
        float r0 = CBB(0), r1 = CBB(1), r2 = CBB(2), r3 = CBB(3);
#pragma unroll
        for (int o = 0; o < 32; o++) {
            float h = px ? acc1[o] : acc0[o];
            c0 += h * CWA(o);
            c1 += h * CWA(32 + o);
            r0 += h * CWB(o);
            r1 += h * CWB(32 + o);
            r2 += h * CWB(64 + o);
            r3 += h * CWB(96 + o);
        }
        float mx = fmaxf(c0, c1);
        float e0 = expf(c0 - mx), e1 = expf(c1 - mx);
        float pr = e1 / (e0 + e1);

        int pix = oy * C3 + oxx;
        g_prob[pix] = pr;
        g_reg[pix] = make_float4(r0, r1, r2, r3);

        if (pr >= 0.6f) {
            int bin = (int)((pr - 0.6f) * 20480.f);
            if (bin > NBINS - 1) bin = NBINS - 1;
            atomicAdd(&g_hist[bin], 1);
        }
    }
}

// ============ KH: find histogram cutoff bin (parallel suffix scan) ============
__global__ void kh() {
    __shared__ int csum[256];
    int t = threadIdx.x;
    int sum = 0;
    for (int b = t * 32; b < t * 32 + 32; b++) sum += g_hist[b];
    csum[t] = sum;
    __syncthreads();
    int chunk = sum;
    for (int off = 1; off < 256; off <<= 1) {
        int v = csum[t] + ((t + off < 256) ? csum[t + off] : 0);
        __syncthreads();
        csum[t] = v;
        __syncthreads();
    }
    int total = csum[0];
    if (t == 0 && total < KTOP) g_cut = 0;
    int suf_excl = (t < 255) ? csum[t + 1] : 0;
    if (suf_excl < KTOP && suf_excl + chunk >= KTOP) {
        int s = suf_excl;
        int B = t * 32;
        for (int b = t * 32 + 31; b >= t * 32; b--) {
            s += g_hist[b];
            if (s >= KTOP) { B = b; break; }
        }
        g_cut = B;
    }
}

// ============ KC: compact candidates >= cutoff bin ============
__global__ void kc() {
    int i = blockIdx.x * 256 + threadIdx.x;
    if (i >= NPIX) return;
    float pr = g_prob[i];
    if (pr < 0.6f) return;
    int bin = (int)((pr - 0.6f) * 20480.f);
    if (bin > NBINS - 1) bin = NBINS - 1;
    if (bin < g_cut) return;
    int pos = atomicAdd(&g_cnt, 1);
    if (pos < CANDMAX) {
        unsigned long long key =
            ((unsigned long long)__float_as_uint(pr) << 32) |
            (unsigned long long)(~(unsigned)i);
        g_cand[pos] = key;
    }
}

// ============ KS: bitonic sort desc + decode boxes ============
__global__ void ks() {
    __shared__ unsigned long long a[CANDMAX];
    int tid = threadIdx.x;
    int cnt = g_cnt;
    if (cnt > CANDMAX) cnt = CANDMAX;
    for (int i = tid; i < CANDMAX; i += 1024) a[i] = (i < cnt) ? g_cand[i] : 0ULL;
    __syncthreads();

    for (int k = 2; k <= CANDMAX; k <<= 1) {
        for (int j = k >> 1; j > 0; j >>= 1) {
            for (int i = tid; i < CANDMAX; i += 1024) {
                int ixj = i ^ j;
                if (ixj > i) {
                    unsigned long long A = a[i], B = a[ixj];
                    bool desc = ((i & k) == 0);
                    if (desc ? (A < B) : (A > B)) { a[i] = B; a[ixj] = A; }
                }
            }
            __syncthreads();
        }
    }

    if (tid < KTOP) {
        unsigned long long key = a[tid];
        unsigned sb = (unsigned)(key >> 32);
        float sc = sb ? __uint_as_float(sb) : -1.0f;
        float x1 = 0.f, y1 = 0.f, x2 = 0.f, y2 = 0.f;
        if (sc >= 0.6f) {
            unsigned idx = ~(unsigned)(key & 0xFFFFFFFFu);
            float4 rg = g_reg[idx];
            float yy = (float)(idx / C3);
            float xx = (float)(idx % C3);
            float cx = (xx * 2.0f + 6.0f) / 0.6f;
            float cy = (yy * 2.0f + 6.0f) / 0.6f;
            const float ww = 12.0f / 0.6f;
            x1 = cx - ww * 0.5f + rg.x * ww;
            y1 = cy - ww * 0.5f + rg.y * ww;
            x2 = cx + ww * 0.5f + rg.z * ww;
            y2 = cy + ww * 0.5f + rg.w * ww;
        }
        g_box5[tid * 5 + 0] = x1;
        g_box5[tid * 5 + 1] = y1;
        g_box5[tid * 5 + 2] = x2;
        g_box5[tid * 5 + 3] = y2;
        g_box5[tid * 5 + 4] = sc;
    }
}

// ============ KM: build suppression bitmasks for both NMS thresholds ============
__global__ void kmask() {
    int i = blockIdx.x;
    int t = threadIdx.x;
    float ax1 = g_box5[i * 5 + 0], ay1 = g_box5[i * 5 + 1];
    float ax2 = g_box5[i * 5 + 2], ay2 = g_box5[i * 5 + 3];
    float bx1 = g_box5[t * 5 + 0], by1 = g_box5[t * 5 + 1];
    float bx2 = g_box5[t * 5 + 2], by2 = g_box5[t * 5 + 3];
    float aar = (ax2 - ax1) * (ay2 - ay1);
    float bar = (bx2 - bx1) * (by2 - by1);
    float xi1 = fmaxf(ax1, bx1), yi1 = fmaxf(ay1, by1);
    float xi2 = fminf(ax2, bx2), yi2 = fminf(ay2, by2);
    float inter = fmaxf(xi2 - xi1, 0.f) * fmaxf(yi2 - yi1, 0.f);
    float iou = inter / (aar + bar - inter + 1e-9f);
    bool gt = (t > i);
    unsigned b0 = __ballot_sync(0xFFFFFFFFu, gt && (iou > 0.5f));
    unsigned b1 = __ballot_sync(0xFFFFFFFFu, gt && (iou > 0.7f));
    if ((t & 31) == 0) {
        g_mask0[i * 16 + (t >> 5)] = b0;
        g_mask1[i * 16 + (t >> 5)] = b1;
    }
}

// ============ KQ: sequential keep-propagation over set bits + output ============
__global__ void kseq(float* __restrict__ out) {
    __shared__ unsigned sm[KTOP * 16];   // 32 KB
    __shared__ unsigned skw[16];
    int t = threadIdx.x;
    float x1 = g_box5[t * 5 + 0];
    float y1 = g_box5[t * 5 + 1];
    float x2 = g_box5[t * 5 + 2];
    float y2 = g_box5[t * 5 + 3];
    float sc = g_box5[t * 5 + 4];
    unsigned bal = __ballot_sync(0xFFFFFFFFu, sc >= 0.6f);
    if ((t & 31) == 0) skw[t >> 5] = bal;

    for (int pass = 0; pass < 2; pass++) {
        const unsigned* gm = pass ? g_mask1 : g_mask0;
        for (int i = t; i < KTOP * 16; i += 512) sm[i] = gm[i];
        __syncthreads();
        if (t < 32) {
            unsigned k = (t < 16) ? skw[t] : 0u;
            for (int w = 0; w < 16; w++) {
                unsigned done = 0;
                while (true) {
                    unsigned cur = __shfl_sync(0xFFFFFFFFu, k, w) & ~done;
                    if (!cur) break;
                    int b = __ffs(cur) - 1;
                    done |= (1u << b);
                    int i = w * 32 + b;
                    unsigned m = (t < 16) ? sm[i * 16 + t] : 0u;
                    k &= ~m;
                }
            }
            if (t < 16) skw[t] = k;
        }
        __syncthreads();
    }

    float m = ((skw[t >> 5] >> (t & 31)) & 1u) ? 1.f : 0.f;
    out[t * 5 + 0] = x1 * m;
    out[t * 5 + 1] = y1 * m;
    out[t * 5 + 2] = x2 * m;
    out[t * 5 + 3] = y2 * m;
    out[t * 5 + 4] = sc * m;
}

// ---------------- host launcher ----------------
extern "C" void kernel_launch(void* const* d_in, const int* in_sizes, int n_in,
                              void* d_out, int out_size) {
    const float* x = (const float*)d_in[0];

    kpack<<<1, 256>>>((const float*)d_in[1], (const float*)d_in[2], (const float*)d_in[3],
                      (const float*)d_in[4], (const float*)d_in[5], (const float*)d_in[6],
                      (const float*)d_in[7], (const float*)d_in[8], (const float*)d_in[9],
                      (const float*)d_in[10], (const float*)d_in[11],
                      (const float*)d_in[12], (const float*)d_in[13]);

    void* sp = 0; cudaGetSymbolAddress(&sp, g_stage);
    cudaMemcpyToSymbolAsync(cAll, sp, NCONST * sizeof(float), 0, cudaMemcpyDeviceToDevice);

    void* hp = 0; cudaGetSymbolAddress(&hp, g_hist);
    cudaMemsetAsync(hp, 0, NBINS * sizeof(int));
    void* cp = 0; cudaGetSymbolAddress(&cp, g_cnt);
    cudaMemsetAsync(cp, 0, sizeof(int));

    dim3 b16(16, 16);
    k1<<<dim3(64, 64), b16>>>(x);
    k2<<<dim3(32, 64), b16>>>();
    k3<<<dim3(32, 64), b16>>>();
    kh<<<1, 256>>>();
    kc<<<(NPIX + 255) / 256, 256>>>();
    ks<<<1, 1024>>>();
    kmask<<<KTOP, KTOP>>>();
    kseq<<<1, 512>>>((float*)d_out);
}

// round 3
// speedup vs baseline: 1.8134x; 1.8134x over previous
#include <cuda_runtime.h>
#include <math.h>
#include <stdint.h>

// ---------------- problem constants ----------------
#define H_IN 2048
#define W_IN 2048
#define P1   1023            // after conv1(2046) + maxpool2
#define C2   1021            // after conv2
#define C3   1019            // after conv3
#define NPIX (C3*C3)         // 1038361
#define NBINS 8192
#define CANDMAX 4096
#define KTOP 512

// ---------------- scratch (device globals) ----------
__device__ float g_pool1[10 * P1 * P1];
__device__ float g_h2[16 * C2 * C2];
__device__ float g_prob[NPIX];
__device__ float4 g_reg[NPIX];
__device__ int   g_hist[NBINS];
__device__ int   g_cut;
__device__ int   g_cnt;
__device__ unsigned long long g_cand[CANDMAX];
__device__ float g_box5[KTOP * 5];
__device__ unsigned g_mask0[KTOP * 16];
__device__ unsigned g_mask1[KTOP * 16];
__device__ float g_stage[6632];

// ---------------- packed constant weights ----------------
#define OW1 0
#define OB1 270
#define OP1 280
#define OW2 290
#define OB2 1730
#define OP2 1746
#define OW3 1762
#define OB3 6370
#define OP3 6402
#define OWA 6434
#define OBA 6498
#define OWB 6500
#define OBB 6628
#define NCONST 6632
__constant__ float cAll[NCONST];

#define CW1(i) cAll[OW1 + (i)]
#define CB1(i) cAll[OB1 + (i)]
#define CP1(i) cAll[OP1 + (i)]
#define CW2(i) cAll[OW2 + (i)]
#define CB2(i) cAll[OB2 + (i)]
#define CP2(i) cAll[OP2 + (i)]
#define CW3(i) cAll[OW3 + (i)]
#define CB3(i) cAll[OB3 + (i)]
#define CP3(i) cAll[OP3 + (i)]
#define CWA(i) cAll[OWA + (i)]
#define CBA(i) cAll[OBA + (i)]
#define CWB(i) cAll[OWB + (i)]
#define CBB(i) cAll[OBB + (i)]

// ============ KP: pack all weights into one staging buffer ============
__global__ void kpack(const float* w1, const float* b1, const float* p1,
                      const float* w2, const float* b2, const float* p2,
                      const float* w3, const float* b3, const float* p3,
                      const float* wa, const float* ba,
                      const float* wb, const float* bb) {
    int t = threadIdx.x;
    for (int i = t; i < 270; i += 256) g_stage[OW1 + i] = w1[i];
    if (t < 10) g_stage[OB1 + t] = b1[t];
    if (t < 10) g_stage[OP1 + t] = p1[t];
    for (int i = t; i < 1440; i += 256) g_stage[OW2 + i] = w2[i];
    if (t < 16) g_stage[OB2 + t] = b2[t];
    if (t < 16) g_stage[OP2 + t] = p2[t];
    for (int i = t; i < 4608; i += 256) g_stage[OW3 + i] = w3[i];
    if (t < 32) g_stage[OB3 + t] = b3[t];
    if (t < 32) g_stage[OP3 + t] = p3[t];
    if (t < 64) g_stage[OWA + t] = wa[t];
    if (t < 2)  g_stage[OBA + t] = ba[t];
    for (int i = t; i < 128; i += 256) g_stage[OWB + i] = wb[i];
    if (t < 4)  g_stage[OBB + t] = bb[t];
}

// ============ K1: conv1(3->10,3x3) + PReLU + maxpool2 fused ============
__global__ __launch_bounds__(256) void k1(const float* __restrict__ x) {
    int j = blockIdx.x * 16 + threadIdx.x;
    int i = blockIdx.y * 16 + threadIdx.y;
    if (i >= P1 || j >= P1) return;

    float p[3][4][4];
#pragma unroll
    for (int c = 0; c < 3; c++) {
        const float* xp = x + c * H_IN * W_IN + (2 * i) * W_IN + 2 * j;
#pragma unroll
        for (int a = 0; a < 4; a++) {
            const float2* rp = reinterpret_cast<const float2*>(xp + a * W_IN);
            float2 u = rp[0], v = rp[1];
            p[c][a][0] = u.x; p[c][a][1] = u.y; p[c][a][2] = v.x; p[c][a][3] = v.y;
        }
    }

#pragma unroll
    for (int co = 0; co < 10; co++) {
        float bb = CB1(co);
        float a00 = bb, a01 = bb, a10 = bb, a11 = bb;
#pragma unroll
        for (int c = 0; c < 3; c++)
#pragma unroll
            for (int dy = 0; dy < 3; dy++)
#pragma unroll
                for (int dx = 0; dx < 3; dx++) {
                    float w = CW1(((co * 3 + c) * 3 + dy) * 3 + dx);
                    a00 += p[c][dy][dx] * w;
                    a01 += p[c][dy][dx + 1] * w;
                    a10 += p[c][dy + 1][dx] * w;
                    a11 += p[c][dy + 1][dx + 1] * w;
                }
        float al = CP1(co);
        a00 = (a00 >= 0.f) ? a00 : al * a00;
        a01 = (a01 >= 0.f) ? a01 : al * a01;
        a10 = (a10 >= 0.f) ? a10 : al * a10;
        a11 = (a11 >= 0.f) ? a11 : al * a11;
        g_pool1[co * P1 * P1 + i * P1 + j] = fmaxf(fmaxf(a00, a01), fmaxf(a10, a11));
    }
}

// ============ K2: conv2(10->16,3x3) + PReLU, 2 px/thread, FULL unroll ============
__global__ __launch_bounds__(256, 3) void k2() {
    __shared__ float s[10][18][36];
    int tx = threadIdx.x, ty = threadIdx.y;
    int tid = ty * 16 + tx;
    int ox0 = blockIdx.x * 32, oy0 = blockIdx.y * 16;

    for (int idx = tid; idx < 10 * 18 * 34; idx += 256) {
        int c = idx / 612;
        int rem = idx - c * 612;
        int r = rem / 34;
        int cc = rem - r * 34;
        int gy = oy0 + r, gx = ox0 + cc;
        s[c][r][cc] = (gy < P1 && gx < P1) ? g_pool1[c * P1 * P1 + gy * P1 + gx] : 0.f;
    }
    __syncthreads();

    int ox = ox0 + tx * 2, oy = oy0 + ty;

    float acc0[16], acc1[16];
#pragma unroll
    for (int o = 0; o < 16; o++) { acc0[o] = CB2(o); acc1[o] = CB2(o); }

#pragma unroll
    for (int c = 0; c < 10; c++) {
        float r[3][4];
#pragma unroll
        for (int dy = 0; dy < 3; dy++) {
            const float2* rp = reinterpret_cast<const float2*>(&s[c][ty + dy][tx * 2]);
            float2 A = rp[0], B = rp[1];
            r[dy][0] = A.x; r[dy][1] = A.y; r[dy][2] = B.x; r[dy][3] = B.y;
        }
#pragma unroll
        for (int o = 0; o < 16; o++)
#pragma unroll
            for (int dy = 0; dy < 3; dy++)
#pragma unroll
                for (int dx = 0; dx < 3; dx++) {
                    float w = CW2(o * 90 + c * 9 + dy * 3 + dx);
                    acc0[o] += r[dy][dx] * w;
                    acc1[o] += r[dy][dx + 1] * w;
                }
    }

    if (oy < C2) {
        int base = oy * C2 + ox;
#pragma unroll
        for (int o = 0; o < 16; o++) {
            float v0 = acc0[o], v1 = acc1[o];
            float al = CP2(o);
            v0 = (v0 >= 0.f) ? v0 : al * v0;
            v1 = (v1 >= 0.f) ? v1 : al * v1;
            if (ox < C2)     g_h2[o * C2 * C2 + base] = v0;
            if (ox + 1 < C2) g_h2[o * C2 * C2 + base + 1] = v1;
        }
    }
}

// ============ K3: conv3(16->32) + PReLU + heads + softmax + hist, 2 px/thread, FULL unroll ============
__global__ __launch_bounds__(256, 2) void k3() {
    __shared__ float s[16][18][36];
    int tx = threadIdx.x, ty = threadIdx.y;
    int tid = ty * 16 + tx;
    int ox0 = blockIdx.x * 32, oy0 = blockIdx.y * 16;

    for (int idx = tid; idx < 16 * 18 * 34; idx += 256) {
        int c = idx / 612;
        int rem = idx - c * 612;
        int r = rem / 34;
        int cc = rem - r * 34;
        int gy = oy0 + r, gx = ox0 + cc;
        s[c][r][cc] = (gy < C2 && gx < C2) ? g_h2[c * C2 * C2 + gy * C2 + gx] : 0.f;
    }
    __syncthreads();

    int ox = ox0 + tx * 2, oy = oy0 + ty;

    float acc0[32], acc1[32];
#pragma unroll
    for (int o = 0; o < 32; o++) { acc0[o] = CB3(o); acc1[o] = CB3(o); }

#pragma unroll
    for (int c = 0; c < 16; c++) {
        float r[3][4];
#pragma unroll
        for (int dy = 0; dy < 3; dy++) {
            const float2* rp = reinterpret_cast<const float2*>(&s[c][ty + dy][tx * 2]);
            float2 A = rp[0], B = rp[1];
            r[dy][0] = A.x; r[dy][1] = A.y; r[dy][2] = B.x; r[dy][3] = B.y;
        }
#pragma unroll
        for (int o = 0; o < 32; o++)
#pragma unroll
            for (int dy = 0; dy < 3; dy++)
#pragma unroll
                for (int dx = 0; dx < 3; dx++) {
                    float w = CW3(o * 144 + c * 9 + dy * 3 + dx);
                    acc0[o] += r[dy][dx] * w;
                    acc1[o] += r[dy][dx + 1] * w;
                }
    }

#pragma unroll
    for (int o = 0; o < 32; o++) {
        float al = CP3(o);
        float v0 = acc0[o], v1 = acc1[o];
        acc0[o] = (v0 >= 0.f) ? v0 : al * v0;
        acc1[o] = (v1 >= 0.f) ? v1 : al * v1;
    }

    if (oy >= C3) return;

#pragma unroll
    for (int px = 0; px < 2; px++) {
        int oxx = ox + px;
        if (oxx >= C3) break;
        float c0 = CBA(0), c1 = CBA(1);
        float r0 = CBB(0), r1 = CBB(1), r2 = CBB(2), r3 = CBB(3);
#pragma unroll
        for (int o = 0; o < 32; o++) {
            float h = px ? acc1[o] : acc0[o];
            c0 += h * CWA(o);
            c1 += h * CWA(32 + o);
            r0 += h * CWB(o);
            r1 += h * CWB(32 + o);
            r2 += h * CWB(64 + o);
            r3 += h * CWB(96 + o);
        }
        float mx = fmaxf(c0, c1);
        float e0 = expf(c0 - mx), e1 = expf(c1 - mx);
        float pr = e1 / (e0 + e1);

        int pix = oy * C3 + oxx;
        g_prob[pix] = pr;
        g_reg[pix] = make_float4(r0, r1, r2, r3);

        if (pr >= 0.6f) {
            int bin = (int)((pr - 0.6f) * 20480.f);
            if (bin > NBINS - 1) bin = NBINS - 1;
            atomicAdd(&g_hist[bin], 1);
        }
    }
}

// ============ KH: find histogram cutoff bin (parallel suffix scan) ============
__global__ void kh() {
    __shared__ int csum[256];
    int t = threadIdx.x;
    int sum = 0;
    for (int b = t * 32; b < t * 32 + 32; b++) sum += g_hist[b];
    csum[t] = sum;
    __syncthreads();
    int chunk = sum;
    for (int off = 1; off < 256; off <<= 1) {
        int v = csum[t] + ((t + off < 256) ? csum[t + off] : 0);
        __syncthreads();
        csum[t] = v;
        __syncthreads();
    }
    int total = csum[0];
    if (t == 0 && total < KTOP) g_cut = 0;
    int suf_excl = (t < 255) ? csum[t + 1] : 0;
    if (suf_excl < KTOP && suf_excl + chunk >= KTOP) {
        int s = suf_excl;
        int B = t * 32;
        for (int b = t * 32 + 31; b >= t * 32; b--) {
            s += g_hist[b];
            if (s >= KTOP) { B = b; break; }
        }
        g_cut = B;
    }
}

// ============ KC: compact candidates >= cutoff bin ============
__global__ void kc() {
    int i = blockIdx.x * 256 + threadIdx.x;
    if (i >= NPIX) return;
    float pr = g_prob[i];
    if (pr < 0.6f) return;
    int bin = (int)((pr - 0.6f) * 20480.f);
    if (bin > NBINS - 1) bin = NBINS - 1;
    if (bin < g_cut) return;
    int pos = atomicAdd(&g_cnt, 1);
    if (pos < CANDMAX) {
        unsigned long long key =
            ((unsigned long long)__float_as_uint(pr) << 32) |
            (unsigned long long)(~(unsigned)i);
        g_cand[pos] = key;
    }
}

// ============ KS: bitonic sort desc + decode boxes ============
__global__ void ks() {
    __shared__ unsigned long long a[CANDMAX];
    int tid = threadIdx.x;
    int cnt = g_cnt;
    if (cnt > CANDMAX) cnt = CANDMAX;
    for (int i = tid; i < CANDMAX; i += 1024) a[i] = (i < cnt) ? g_cand[i] : 0ULL;
    __syncthreads();

    for (int k = 2; k <= CANDMAX; k <<= 1) {
        for (int j = k >> 1; j > 0; j >>= 1) {
            for (int i = tid; i < CANDMAX; i += 1024) {
                int ixj = i ^ j;
                if (ixj > i) {
                    unsigned long long A = a[i], B = a[ixj];
                    bool desc = ((i & k) == 0);
                    if (desc ? (A < B) : (A > B)) { a[i] = B; a[ixj] = A; }
                }
            }
            __syncthreads();
        }
    }

    if (tid < KTOP) {
        unsigned long long key = a[tid];
        unsigned sb = (unsigned)(key >> 32);
        float sc = sb ? __uint_as_float(sb) : -1.0f;
        float x1 = 0.f, y1 = 0.f, x2 = 0.f, y2 = 0.f;
        if (sc >= 0.6f) {
            unsigned idx = ~(unsigned)(key & 0xFFFFFFFFu);
            float4 rg = g_reg[idx];
            float yy = (float)(idx / C3);
            float xx = (float)(idx % C3);
            float cx = (xx * 2.0f + 6.0f) / 0.6f;
            float cy = (yy * 2.0f + 6.0f) / 0.6f;
            const float ww = 12.0f / 0.6f;
            x1 = cx - ww * 0.5f + rg.x * ww;
            y1 = cy - ww * 0.5f + rg.y * ww;
            x2 = cx + ww * 0.5f + rg.z * ww;
            y2 = cy + ww * 0.5f + rg.w * ww;
        }
        g_box5[tid * 5 + 0] = x1;
        g_box5[tid * 5 + 1] = y1;
        g_box5[tid * 5 + 2] = x2;
        g_box5[tid * 5 + 3] = y2;
        g_box5[tid * 5 + 4] = sc;
    }
}

// ============ KM: build suppression bitmasks for both NMS thresholds ============
__global__ void kmask() {
    int i = blockIdx.x;
    int t = threadIdx.x;
    float ax1 = g_box5[i * 5 + 0], ay1 = g_box5[i * 5 + 1];
    float ax2 = g_box5[i * 5 + 2], ay2 = g_box5[i * 5 + 3];
    float bx1 = g_box5[t * 5 + 0], by1 = g_box5[t * 5 + 1];
    float bx2 = g_box5[t * 5 + 2], by2 = g_box5[t * 5 + 3];
    float aar = (ax2 - ax1) * (ay2 - ay1);
    float bar = (bx2 - bx1) * (by2 - by1);
    float xi1 = fmaxf(ax1, bx1), yi1 = fmaxf(ay1, by1);
    float xi2 = fminf(ax2, bx2), yi2 = fminf(ay2, by2);
    float inter = fmaxf(xi2 - xi1, 0.f) * fmaxf(yi2 - yi1, 0.f);
    float iou = inter / (aar + bar - inter + 1e-9f);
    bool gt = (t > i);
    unsigned b0 = __ballot_sync(0xFFFFFFFFu, gt && (iou > 0.5f));
    unsigned b1 = __ballot_sync(0xFFFFFFFFu, gt && (iou > 0.7f));
    if ((t & 31) == 0) {
        g_mask0[i * 16 + (t >> 5)] = b0;
        g_mask1[i * 16 + (t >> 5)] = b1;
    }
}

// ============ KQ: sequential keep-propagation over set bits + output ============
__global__ void kseq(float* __restrict__ out) {
    __shared__ unsigned sm[KTOP * 16];   // 32 KB
    __shared__ unsigned skw[16];
    int t = threadIdx.x;
    float x1 = g_box5[t * 5 + 0];
    float y1 = g_box5[t * 5 + 1];
    float x2 = g_box5[t * 5 + 2];
    float y2 = g_box5[t * 5 + 3];
    float sc = g_box5[t * 5 + 4];
    unsigned bal = __ballot_sync(0xFFFFFFFFu, sc >= 0.6f);
    if ((t & 31) == 0) skw[t >> 5] = bal;

    for (int pass = 0; pass < 2; pass++) {
        const unsigned* gm = pass ? g_mask1 : g_mask0;
        for (int i = t; i < KTOP * 16; i += 512) sm[i] = gm[i];
        __syncthreads();
        if (t < 32) {
            unsigned k = (t < 16) ? skw[t] : 0u;
            for (int w = 0; w < 16; w++) {
                unsigned done = 0;
                while (true) {
                    unsigned cur = __shfl_sync(0xFFFFFFFFu, k, w) & ~done;
                    if (!cur) break;
                    int b = __ffs(cur) - 1;
                    done |= (1u << b);
                    int i = w * 32 + b;
                    unsigned m = (t < 16) ? sm[i * 16 + t] : 0u;
                    k &= ~m;
                }
            }
            if (t < 16) skw[t] = k;
        }
        __syncthreads();
    }

    float m = ((skw[t >> 5] >> (t & 31)) & 1u) ? 1.f : 0.f;
    out[t * 5 + 0] = x1 * m;
    out[t * 5 + 1] = y1 * m;
    out[t * 5 + 2] = x2 * m;
    out[t * 5 + 3] = y2 * m;
    out[t * 5 + 4] = sc * m;
}

// ---------------- host launcher ----------------
extern "C" void kernel_launch(void* const* d_in, const int* in_sizes, int n_in,
                              void* d_out, int out_size) {
    const float* x = (const float*)d_in[0];

    kpack<<<1, 256>>>((const float*)d_in[1], (const float*)d_in[2], (const float*)d_in[3],
                      (const float*)d_in[4], (const float*)d_in[5], (const float*)d_in[6],
                      (const float*)d_in[7], (const float*)d_in[8], (const float*)d_in[9],
                      (const float*)d_in[10], (const float*)d_in[11],
                      (const float*)d_in[12], (const float*)d_in[13]);

    void* sp = 0; cudaGetSymbolAddress(&sp, g_stage);
    cudaMemcpyToSymbolAsync(cAll, sp, NCONST * sizeof(float), 0, cudaMemcpyDeviceToDevice);

    void* hp = 0; cudaGetSymbolAddress(&hp, g_hist);
    cudaMemsetAsync(hp, 0, NBINS * sizeof(int));
    void* cp = 0; cudaGetSymbolAddress(&cp, g_cnt);
    cudaMemsetAsync(cp, 0, sizeof(int));

    dim3 b16(16, 16);
    k1<<<dim3(64, 64), b16>>>(x);
    k2<<<dim3(32, 64), b16>>>();
    k3<<<dim3(32, 64), b16>>>();
    kh<<<1, 256>>>();
    kc<<<(NPIX + 255) / 256, 256>>>();
    ks<<<1, 1024>>>();
    kmask<<<KTOP, KTOP>>>();
    kseq<<<1, 512>>>((float*)d_out);
}

// round 4
// speedup vs baseline: 3.6506x; 2.0131x over previous
#include <cuda_runtime.h>
#include <math.h>
#include <stdint.h>

// ---------------- problem constants ----------------
#define H_IN 2048
#define W_IN 2048
#define P1   1023            // after conv1(2046) + maxpool2
#define C2   1021            // after conv2
#define C3   1019            // after conv3
#define NPIX (C3*C3)         // 1038361
#define NBINS 8192
#define CANDMAX 4096
#define KTOP 512

// ---------------- scratch (device globals) ----------
__device__ float g_pool1[10 * P1 * P1];
__device__ float g_h2[16 * C2 * C2];
__device__ float g_prob[NPIX];
__device__ float4 g_reg[NPIX];
__device__ int   g_hist[NBINS];
__device__ int   g_cut;
__device__ int   g_cnt;
__device__ unsigned long long g_cand[CANDMAX];
__device__ float g_box5[KTOP * 5];
__device__ unsigned g_mask0[KTOP * 16];
__device__ unsigned g_mask1[KTOP * 16];
__device__ float g_stage[6632];
// duplicated {w,w} weights, padded to 10 per (c,o) group for 16B-aligned LDS.128
__device__ float4 g_wd2[10 * 16 * 10 / 2];   // 800 float4
__device__ float4 g_wd3[16 * 32 * 10 / 2];   // 2560 float4

// ---------------- packed constant weights (k1 + biases/prelu/heads) -------
#define OW1 0
#define OB1 270
#define OP1 280
#define OW2 290
#define OB2 1730
#define OP2 1746
#define OW3 1762
#define OB3 6370
#define OP3 6402
#define OWA 6434
#define OBA 6498
#define OWB 6500
#define OBB 6628
#define NCONST 6632
__constant__ float cAll[NCONST];

#define CW1(i) cAll[OW1 + (i)]
#define CB1(i) cAll[OB1 + (i)]
#define CP1(i) cAll[OP1 + (i)]
#define CB2(i) cAll[OB2 + (i)]
#define CP2(i) cAll[OP2 + (i)]
#define CB3(i) cAll[OB3 + (i)]
#define CP3(i) cAll[OP3 + (i)]
#define CWA(i) cAll[OWA + (i)]
#define CBA(i) cAll[OBA + (i)]
#define CWB(i) cAll[OWB + (i)]
#define CBB(i) cAll[OBB + (i)]

// ---------------- f32x2 helpers ----------------
typedef unsigned long long ull;

__device__ __forceinline__ ull pk2(float lo, float hi) {
    ull r; asm("mov.b64 %0, {%1, %2};" : "=l"(r) : "f"(lo), "f"(hi)); return r;
}
__device__ __forceinline__ void up2(float& lo, float& hi, ull v) {
    asm("mov.b64 {%0, %1}, %2;" : "=f"(lo), "=f"(hi) : "l"(v));
}
__device__ __forceinline__ void ffma2(ull& d, ull a, ull b) {
    asm("fma.rn.f32x2 %0, %1, %2, %0;" : "+l"(d) : "l"(a), "l"(b));
}

// ============ KP: pack weights: staging + duplicated smem-source arrays ====
__global__ void kpack(const float* w1, const float* b1, const float* p1,
                      const float* w2, const float* b2, const float* p2,
                      const float* w3, const float* b3, const float* p3,
                      const float* wa, const float* ba,
                      const float* wb, const float* bb) {
    int t = threadIdx.x;
    for (int i = t; i < 270; i += 256) g_stage[OW1 + i] = w1[i];
    if (t < 10) g_stage[OB1 + t] = b1[t];
    if (t < 10) g_stage[OP1 + t] = p1[t];
    for (int i = t; i < 1440; i += 256) g_stage[OW2 + i] = w2[i];
    if (t < 16) g_stage[OB2 + t] = b2[t];
    if (t < 16) g_stage[OP2 + t] = p2[t];
    for (int i = t; i < 4608; i += 256) g_stage[OW3 + i] = w3[i];
    if (t < 32) g_stage[OB3 + t] = b3[t];
    if (t < 32) g_stage[OP3 + t] = p3[t];
    if (t < 64) g_stage[OWA + t] = wa[t];
    if (t < 2)  g_stage[OBA + t] = ba[t];
    for (int i = t; i < 128; i += 256) g_stage[OWB + i] = wb[i];
    if (t < 4)  g_stage[OBB + t] = bb[t];

    // k2 duplicated weights: wd2[(c*16+o)*10 + k] = {w,w}
    float* d2 = (float*)g_wd2;
    for (int idx = t; idx < 1440; idx += 256) {
        int k = idx % 9, rest = idx / 9;
        int o = rest % 16, c = rest / 16;
        float w = w2[o * 90 + c * 9 + k];
        int g = (c * 16 + o) * 10 + k;
        d2[g * 2] = w; d2[g * 2 + 1] = w;
    }
    for (int g = t; g < 160; g += 256) {        // zero pads
        d2[(g * 10 + 9) * 2] = 0.f; d2[(g * 10 + 9) * 2 + 1] = 0.f;
    }
    // k3 duplicated weights: wd3[(c*32+o)*10 + k] = {w,w}
    float* d3 = (float*)g_wd3;
    for (int idx = t; idx < 4608; idx += 256) {
        int k = idx % 9, rest = idx / 9;
        int o = rest % 32, c = rest / 32;
        float w = w3[o * 144 + c * 9 + k];
        int g = (c * 32 + o) * 10 + k;
        d3[g * 2] = w; d3[g * 2 + 1] = w;
    }
    for (int g = t; g < 512; g += 256) {
        d3[(g * 10 + 9) * 2] = 0.f; d3[(g * 10 + 9) * 2 + 1] = 0.f;
    }
}

// ============ K1: conv1(3->10,3x3) + PReLU + maxpool2 (const weights, 1KB) ==
__global__ __launch_bounds__(256) void k1(const float* __restrict__ x) {
    int j = blockIdx.x * 16 + threadIdx.x;
    int i = blockIdx.y * 16 + threadIdx.y;
    if (i >= P1 || j >= P1) return;

    float p[3][4][4];
#pragma unroll
    for (int c = 0; c < 3; c++) {
        const float* xp = x + c * H_IN * W_IN + (2 * i) * W_IN + 2 * j;
#pragma unroll
        for (int a = 0; a < 4; a++) {
            const float2* rp = reinterpret_cast<const float2*>(xp + a * W_IN);
            float2 u = rp[0], v = rp[1];
            p[c][a][0] = u.x; p[c][a][1] = u.y; p[c][a][2] = v.x; p[c][a][3] = v.y;
        }
    }

#pragma unroll
    for (int co = 0; co < 10; co++) {
        float bb = CB1(co);
        float a00 = bb, a01 = bb, a10 = bb, a11 = bb;
#pragma unroll
        for (int c = 0; c < 3; c++)
#pragma unroll
            for (int dy = 0; dy < 3; dy++)
#pragma unroll
                for (int dx = 0; dx < 3; dx++) {
                    float w = CW1(((co * 3 + c) * 3 + dy) * 3 + dx);
                    a00 += p[c][dy][dx] * w;
                    a01 += p[c][dy][dx + 1] * w;
                    a10 += p[c][dy + 1][dx] * w;
                    a11 += p[c][dy + 1][dx + 1] * w;
                }
        float al = CP1(co);
        a00 = (a00 >= 0.f) ? a00 : al * a00;
        a01 = (a01 >= 0.f) ? a01 : al * a01;
        a10 = (a10 >= 0.f) ? a10 : al * a10;
        a11 = (a11 >= 0.f) ? a11 : al * a11;
        g_pool1[co * P1 * P1 + i * P1 + j] = fmaxf(fmaxf(a00, a01), fmaxf(a10, a11));
    }
}

// ============ K2: conv2(10->16) + PReLU, f32x2, smem weights ============
__global__ __launch_bounds__(256, 2) void k2() {
    __shared__ float s[10][18][36];
    __shared__ __align__(16) float2 wdup[10 * 16 * 10];
    int tx = threadIdx.x, ty = threadIdx.y;
    int tid = ty * 16 + tx;
    int ox0 = blockIdx.x * 32, oy0 = blockIdx.y * 16;

    {
        float4* wv = (float4*)wdup;
        for (int i = tid; i < 800; i += 256) wv[i] = g_wd2[i];
    }
    for (int idx = tid; idx < 10 * 18 * 34; idx += 256) {
        int c = idx / 612;
        int rem = idx - c * 612;
        int r = rem / 34;
        int cc = rem - r * 34;
        int gy = oy0 + r, gx = ox0 + cc;
        s[c][r][cc] = (gy < P1 && gx < P1) ? g_pool1[c * P1 * P1 + gy * P1 + gx] : 0.f;
    }
    __syncthreads();

    int ox = ox0 + tx * 2, oy = oy0 + ty;

    ull acc[16];
#pragma unroll
    for (int o = 0; o < 16; o++) acc[o] = pk2(CB2(o), CB2(o));

    const ull* wsm = (const ull*)wdup;
#pragma unroll 1
    for (int c = 0; c < 10; c++) {
        float r[3][4];
#pragma unroll
        for (int dy = 0; dy < 3; dy++) {
            const float2* rp = reinterpret_cast<const float2*>(&s[c][ty + dy][tx * 2]);
            float2 A = rp[0], B = rp[1];
            r[dy][0] = A.x; r[dy][1] = A.y; r[dy][2] = B.x; r[dy][3] = B.y;
        }
        ull t2[9];
#pragma unroll
        for (int dy = 0; dy < 3; dy++)
#pragma unroll
            for (int dx = 0; dx < 3; dx++)
                t2[dy * 3 + dx] = pk2(r[dy][dx], r[dy][dx + 1]);

        const ull* wc = wsm + c * 160;
#pragma unroll
        for (int o = 0; o < 16; o++) {
            const ull* w = wc + o * 10;
            ulonglong2 p0 = *(const ulonglong2*)(w + 0);
            ulonglong2 p1 = *(const ulonglong2*)(w + 2);
            ulonglong2 p2 = *(const ulonglong2*)(w + 4);
            ulonglong2 p3 = *(const ulonglong2*)(w + 6);
            ull p8 = w[8];
            ffma2(acc[o], t2[0], p0.x);
            ffma2(acc[o], t2[1], p0.y);
            ffma2(acc[o], t2[2], p1.x);
            ffma2(acc[o], t2[3], p1.y);
            ffma2(acc[o], t2[4], p2.x);
            ffma2(acc[o], t2[5], p2.y);
            ffma2(acc[o], t2[6], p3.x);
            ffma2(acc[o], t2[7], p3.y);
            ffma2(acc[o], t2[8], p8);
        }
    }

    if (oy < C2) {
        int base = oy * C2 + ox;
#pragma unroll
        for (int o = 0; o < 16; o++) {
            float v0, v1;
            up2(v0, v1, acc[o]);
            float al = CP2(o);
            v0 = (v0 >= 0.f) ? v0 : al * v0;
            v1 = (v1 >= 0.f) ? v1 : al * v1;
            if (ox < C2)     g_h2[o * C2 * C2 + base] = v0;
            if (ox + 1 < C2) g_h2[o * C2 * C2 + base + 1] = v1;
        }
    }
}

// ============ K3: conv3(16->32) + PReLU + heads + softmax + hist, f32x2 ====
#define K3_TILE (16 * 18 * 36)
#define K3_SMEM_BYTES (K3_TILE * 4 + 16 * 32 * 10 * 8)

__global__ __launch_bounds__(256, 2) void k3() {
    extern __shared__ float dyn[];
    float (*s)[18][36] = (float(*)[18][36])dyn;
    ull* wsm = (ull*)(dyn + K3_TILE);

    int tx = threadIdx.x, ty = threadIdx.y;
    int tid = ty * 16 + tx;
    int ox0 = blockIdx.x * 32, oy0 = blockIdx.y * 16;

    {
        float4* wv = (float4*)wsm;
        for (int i = tid; i < 2560; i += 256) wv[i] = g_wd3[i];
    }
    for (int idx = tid; idx < 16 * 18 * 34; idx += 256) {
        int c = idx / 612;
        int rem = idx - c * 612;
        int r = rem / 34;
        int cc = rem - r * 34;
        int gy = oy0 + r, gx = ox0 + cc;
        s[c][r][cc] = (gy < C2 && gx < C2) ? g_h2[c * C2 * C2 + gy * C2 + gx] : 0.f;
    }
    __syncthreads();

    int ox = ox0 + tx * 2, oy = oy0 + ty;

    ull acc[32];
#pragma unroll
    for (int o = 0; o < 32; o++) acc[o] = pk2(CB3(o), CB3(o));

#pragma unroll 1
    for (int c = 0; c < 16; c++) {
        float r[3][4];
#pragma unroll
        for (int dy = 0; dy < 3; dy++) {
            const float2* rp = reinterpret_cast<const float2*>(&s[c][ty + dy][tx * 2]);
            float2 A = rp[0], B = rp[1];
            r[dy][0] = A.x; r[dy][1] = A.y; r[dy][2] = B.x; r[dy][3] = B.y;
        }
        ull t2[9];
#pragma unroll
        for (int dy = 0; dy < 3; dy++)
#pragma unroll
            for (int dx = 0; dx < 3; dx++)
                t2[dy * 3 + dx] = pk2(r[dy][dx], r[dy][dx + 1]);

        const ull* wc = wsm + c * 320;
#pragma unroll
        for (int o = 0; o < 32; o++) {
            const ull* w = wc + o * 10;
            ulonglong2 p0 = *(const ulonglong2*)(w + 0);
            ulonglong2 p1 = *(const ulonglong2*)(w + 2);
            ulonglong2 p2 = *(const ulonglong2*)(w + 4);
            ulonglong2 p3 = *(const ulonglong2*)(w + 6);
            ull p8 = w[8];
            ffma2(acc[o], t2[0], p0.x);
            ffma2(acc[o], t2[1], p0.y);
            ffma2(acc[o], t2[2], p1.x);
            ffma2(acc[o], t2[3], p1.y);
            ffma2(acc[o], t2[4], p2.x);
            ffma2(acc[o], t2[5], p2.y);
            ffma2(acc[o], t2[6], p3.x);
            ffma2(acc[o], t2[7], p3.y);
            ffma2(acc[o], t2[8], p8);
        }
    }

    if (oy >= C3) return;

    float h0[32], h1[32];
#pragma unroll
    for (int o = 0; o < 32; o++) {
        float v0, v1;
        up2(v0, v1, acc[o]);
        float al = CP3(o);
        h0[o] = (v0 >= 0.f) ? v0 : al * v0;
        h1[o] = (v1 >= 0.f) ? v1 : al * v1;
    }

#pragma unroll
    for (int px = 0; px < 2; px++) {
        int oxx = ox + px;
        if (oxx >= C3) break;
        float c0 = CBA(0), c1 = CBA(1);
        float r0 = CBB(0), r1 = CBB(1), r2 = CBB(2), r3 = CBB(3);
#pragma unroll
        for (int o = 0; o < 32; o++) {
            float h = px ? h1[o] : h0[o];
            c0 += h * CWA(o);
            c1 += h * CWA(32 + o);
            r0 += h * CWB(o);
            r1 += h * CWB(32 + o);
            r2 += h * CWB(64 + o);
            r3 += h * CWB(96 + o);
        }
        float mx = fmaxf(c0, c1);
        float e0 = expf(c0 - mx), e1 = expf(c1 - mx);
        float pr = e1 / (e0 + e1);

        int pix = oy * C3 + oxx;
        g_prob[pix] = pr;
        g_reg[pix] = make_float4(r0, r1, r2, r3);

        if (pr >= 0.6f) {
            int bin = (int)((pr - 0.6f) * 20480.f);
            if (bin > NBINS - 1) bin = NBINS - 1;
            atomicAdd(&g_hist[bin], 1);
        }
    }
}

// ============ KH: find histogram cutoff bin (parallel suffix scan) ============
__global__ void kh() {
    __shared__ int csum[256];
    int t = threadIdx.x;
    int sum = 0;
    for (int b = t * 32; b < t * 32 + 32; b++) sum += g_hist[b];
    csum[t] = sum;
    __syncthreads();
    int chunk = sum;
    for (int off = 1; off < 256; off <<= 1) {
        int v = csum[t] + ((t + off < 256) ? csum[t + off] : 0);
        __syncthreads();
        csum[t] = v;
        __syncthreads();
    }
    int total = csum[0];
    if (t == 0 && total < KTOP) g_cut = 0;
    int suf_excl = (t < 255) ? csum[t + 1] : 0;
    if (suf_excl < KTOP && suf_excl + chunk >= KTOP) {
        int s = suf_excl;
        int B = t * 32;
        for (int b = t * 32 + 31; b >= t * 32; b--) {
            s += g_hist[b];
            if (s >= KTOP) { B = b; break; }
        }
        g_cut = B;
    }
}

// ============ KC: compact candidates >= cutoff bin ============
__global__ void kc() {
    int i = blockIdx.x * 256 + threadIdx.x;
    if (i >= NPIX) return;
    float pr = g_prob[i];
    if (pr < 0.6f) return;
    int bin = (int)((pr - 0.6f) * 20480.f);
    if (bin > NBINS - 1) bin = NBINS - 1;
    if (bin < g_cut) return;
    int pos = atomicAdd(&g_cnt, 1);
    if (pos < CANDMAX) {
        unsigned long long key =
            ((unsigned long long)__float_as_uint(pr) << 32) |
            (unsigned long long)(~(unsigned)i);
        g_cand[pos] = key;
    }
}

// ============ KS: bitonic sort desc + decode boxes ============
__global__ void ks() {
    __shared__ unsigned long long a[CANDMAX];
    int tid = threadIdx.x;
    int cnt = g_cnt;
    if (cnt > CANDMAX) cnt = CANDMAX;
    for (int i = tid; i < CANDMAX; i += 1024) a[i] = (i < cnt) ? g_cand[i] : 0ULL;
    __syncthreads();

    for (int k = 2; k <= CANDMAX; k <<= 1) {
        for (int j = k >> 1; j > 0; j >>= 1) {
            for (int i = tid; i < CANDMAX; i += 1024) {
                int ixj = i ^ j;
                if (ixj > i) {
                    unsigned long long A = a[i], B = a[ixj];
                    bool desc = ((i & k) == 0);
                    if (desc ? (A < B) : (A > B)) { a[i] = B; a[ixj] = A; }
                }
            }
            __syncthreads();
        }
    }

    if (tid < KTOP) {
        unsigned long long key = a[tid];
        unsigned sb = (unsigned)(key >> 32);
        float sc = sb ? __uint_as_float(sb) : -1.0f;
        float x1 = 0.f, y1 = 0.f, x2 = 0.f, y2 = 0.f;
        if (sc >= 0.6f) {
            unsigned idx = ~(unsigned)(key & 0xFFFFFFFFu);
            float4 rg = g_reg[idx];
            float yy = (float)(idx / C3);
            float xx = (float)(idx % C3);
            float cx = (xx * 2.0f + 6.0f) / 0.6f;
            float cy = (yy * 2.0f + 6.0f) / 0.6f;
            const float ww = 12.0f / 0.6f;
            x1 = cx - ww * 0.5f + rg.x * ww;
            y1 = cy - ww * 0.5f + rg.y * ww;
            x2 = cx + ww * 0.5f + rg.z * ww;
            y2 = cy + ww * 0.5f + rg.w * ww;
        }
        g_box5[tid * 5 + 0] = x1;
        g_box5[tid * 5 + 1] = y1;
        g_box5[tid * 5 + 2] = x2;
        g_box5[tid * 5 + 3] = y2;
        g_box5[tid * 5 + 4] = sc;
    }
}

// ============ KM: build suppression bitmasks for both NMS thresholds ============
__global__ void kmask() {
    int i = blockIdx.x;
    int t = threadIdx.x;
    float ax1 = g_box5[i * 5 + 0], ay1 = g_box5[i * 5 + 1];
    float ax2 = g_box5[i * 5 + 2], ay2 = g_box5[i * 5 + 3];
    float bx1 = g_box5[t * 5 + 0], by1 = g_box5[t * 5 + 1];
    float bx2 = g_box5[t * 5 + 2], by2 = g_box5[t * 5 + 3];
    float aar = (ax2 - ax1) * (ay2 - ay1);
    float bar = (bx2 - bx1) * (by2 - by1);
    float xi1 = fmaxf(ax1, bx1), yi1 = fmaxf(ay1, by1);
    float xi2 = fminf(ax2, bx2), yi2 = fminf(ay2, by2);
    float inter = fmaxf(xi2 - xi1, 0.f) * fmaxf(yi2 - yi1, 0.f);
    float iou = inter / (aar + bar - inter + 1e-9f);
    bool gt = (t > i);
    unsigned b0 = __ballot_sync(0xFFFFFFFFu, gt && (iou > 0.5f));
    unsigned b1 = __ballot_sync(0xFFFFFFFFu, gt && (iou > 0.7f));
    if ((t & 31) == 0) {
        g_mask0[i * 16 + (t >> 5)] = b0;
        g_mask1[i * 16 + (t >> 5)] = b1;
    }
}

// ============ KQ: sequential keep-propagation over set bits + output ============
__global__ void kseq(float* __restrict__ out) {
    __shared__ unsigned sm[KTOP * 16];
    __shared__ unsigned skw[16];
    int t = threadIdx.x;
    float x1 = g_box5[t * 5 + 0];
    float y1 = g_box5[t * 5 + 1];
    float x2 = g_box5[t * 5 + 2];
    float y2 = g_box5[t * 5 + 3];
    float sc = g_box5[t * 5 + 4];
    unsigned bal = __ballot_sync(0xFFFFFFFFu, sc >= 0.6f);
    if ((t & 31) == 0) skw[t >> 5] = bal;

    for (int pass = 0; pass < 2; pass++) {
        const unsigned* gm = pass ? g_mask1 : g_mask0;
        for (int i = t; i < KTOP * 16; i += 512) sm[i] = gm[i];
        __syncthreads();
        if (t < 32) {
            unsigned k = (t < 16) ? skw[t] : 0u;
            for (int w = 0; w < 16; w++) {
                unsigned done = 0;
                while (true) {
                    unsigned cur = __shfl_sync(0xFFFFFFFFu, k, w) & ~done;
                    if (!cur) break;
                    int b = __ffs(cur) - 1;
                    done |= (1u << b);
                    int i = w * 32 + b;
                    unsigned m = (t < 16) ? sm[i * 16 + t] : 0u;
                    k &= ~m;
                }
            }
            if (t < 16) skw[t] = k;
        }
        __syncthreads();
    }

    float m = ((skw[t >> 5] >> (t & 31)) & 1u) ? 1.f : 0.f;
    out[t * 5 + 0] = x1 * m;
    out[t * 5 + 1] = y1 * m;
    out[t * 5 + 2] = x2 * m;
    out[t * 5 + 3] = y2 * m;
    out[t * 5 + 4] = sc * m;
}

// ---------------- host launcher ----------------
extern "C" void kernel_launch(void* const* d_in, const int* in_sizes, int n_in,
                              void* d_out, int out_size) {
    const float* x = (const float*)d_in[0];

    kpack<<<1, 256>>>((const float*)d_in[1], (const float*)d_in[2], (const float*)d_in[3],
                      (const float*)d_in[4], (const float*)d_in[5], (const float*)d_in[6],
                      (const float*)d_in[7], (const float*)d_in[8], (const float*)d_in[9],
                      (const float*)d_in[10], (const float*)d_in[11],
                      (const float*)d_in[12], (const float*)d_in[13]);

    void* sp = 0; cudaGetSymbolAddress(&sp, g_stage);
    cudaMemcpyToSymbolAsync(cAll, sp, NCONST * sizeof(float), 0, cudaMemcpyDeviceToDevice);

    void* hp = 0; cudaGetSymbolAddress(&hp, g_hist);
    cudaMemsetAsync(hp, 0, NBINS * sizeof(int));
    void* cp = 0; cudaGetSymbolAddress(&cp, g_cnt);
    cudaMemsetAsync(cp, 0, sizeof(int));

    cudaFuncSetAttribute(k3, cudaFuncAttributeMaxDynamicSharedMemorySize, K3_SMEM_BYTES);

    dim3 b16(16, 16);
    k1<<<dim3(64, 64), b16>>>(x);
    k2<<<dim3(32, 64), b16>>>();
    k3<<<dim3(32, 64), b16, K3_SMEM_BYTES>>>();
    kh<<<1, 256>>>();
    kc<<<(NPIX + 255) / 256, 256>>>();
    ks<<<1, 1024>>>();
    kmask<<<KTOP, KTOP>>>();
    kseq<<<1, 512>>>((float*)d_out);
}